// round 10
// baseline (speedup 1.0000x reference)
#include <cuda_runtime.h>
#include <math.h>
#include <stdint.h>

#define T_TOK 2048
#define H_DIM 1024
#define E_NUM 8
#define I_DIM 2048

// ---------------- device scratch ----------------
__device__ int   g_count[E_NUM];
__device__ int   g_tok[E_NUM][T_TOK];
__device__ float g_wt[E_NUM][T_TOK];
__device__ int   g_slot[T_TOK][2];
__device__ float g_act[(size_t)E_NUM * T_TOK * I_DIM];   // 128 MB (tf32-rounded values)
__device__ float g_y[(size_t)E_NUM * T_TOK * H_DIM];     // 64 MB

// ---------------- helpers ----------------
__device__ __forceinline__ uint32_t to_tf32(float x) {
    uint32_t r; asm("cvt.rna.tf32.f32 %0, %1;" : "=r"(r) : "f"(x)); return r;
}
__device__ __forceinline__ float to_tf32f(float x) {
    return __uint_as_float(to_tf32(x));
}
__device__ __forceinline__ void mma_tf32(float* c, const uint32_t* a, const uint32_t* b) {
    asm volatile(
        "mma.sync.aligned.m16n8k8.row.col.f32.tf32.tf32.f32 "
        "{%0,%1,%2,%3}, {%4,%5,%6,%7}, {%8,%9}, {%0,%1,%2,%3};"
        : "+f"(c[0]), "+f"(c[1]), "+f"(c[2]), "+f"(c[3])
        : "r"(a[0]), "r"(a[1]), "r"(a[2]), "r"(a[3]), "r"(b[0]), "r"(b[1]));
}
// A-stage swizzle (validated R7)
__device__ __forceinline__ int aswz(int u, int ks) {
    return u ^ ((ks << 1) ^ ((u >> 3) & 3));
}

// ---------------- small kernels ----------------
__global__ void zero_counts_kernel() {
    if (threadIdx.x < E_NUM) g_count[threadIdx.x] = 0;
}

__global__ void router_kernel(const float* __restrict__ hs, const float* __restrict__ gw) {
    int t = blockIdx.x;
    const float* x = hs + (size_t)t * H_DIM;
    float acc[E_NUM];
#pragma unroll
    for (int e = 0; e < E_NUM; e++) acc[e] = 0.f;
    for (int j = threadIdx.x; j < H_DIM; j += blockDim.x) {
        float xv = x[j];
        const float4* grow = reinterpret_cast<const float4*>(gw + (size_t)j * E_NUM);
        float4 g0 = grow[0], g1 = grow[1];
        acc[0] += xv * g0.x; acc[1] += xv * g0.y; acc[2] += xv * g0.z; acc[3] += xv * g0.w;
        acc[4] += xv * g1.x; acc[5] += xv * g1.y; acc[6] += xv * g1.z; acc[7] += xv * g1.w;
    }
#pragma unroll
    for (int off = 16; off > 0; off >>= 1)
#pragma unroll
        for (int e = 0; e < E_NUM; e++)
            acc[e] += __shfl_xor_sync(0xffffffffu, acc[e], off);
    __shared__ float s[4][E_NUM];
    int warp = threadIdx.x >> 5, lane = threadIdx.x & 31;
    if (lane == 0)
#pragma unroll
        for (int e = 0; e < E_NUM; e++) s[warp][e] = acc[e];
    __syncthreads();
    if (threadIdx.x == 0) {
        float l[E_NUM];
#pragma unroll
        for (int e = 0; e < E_NUM; e++)
            l[e] = tanhf((s[0][e] + s[1][e] + s[2][e] + s[3][e]) * (1.0f / 30.0f));
        int i0 = 0;
#pragma unroll
        for (int e = 1; e < E_NUM; e++) if (l[e] > l[i0]) i0 = e;
        int i1 = (i0 == 0) ? 1 : 0;
#pragma unroll
        for (int e = 0; e < E_NUM; e++) if (e != i0 && l[e] > l[i1]) i1 = e;
        float d  = l[i1] - l[i0];
        float ed = expf(d);
        float inv = 1.0f / (1.0f + ed);
        float p0 = inv, p1 = ed * inv;
        int p = atomicAdd(&g_count[i0], 1);
        g_tok[i0][p] = t; g_wt[i0][p] = p0; g_slot[t][0] = i0 * T_TOK + p;
        p = atomicAdd(&g_count[i1], 1);
        g_tok[i1][p] = t; g_wt[i1][p] = p1; g_slot[t][1] = i1 * T_TOK + p;
    }
}

__device__ __forceinline__ float gelu_tanh(float g) {
    float c = 0.7978845608028654f * (g + 0.044715f * g * g * g);
    return 0.5f * g * (1.0f + tanhf(c));
}

// ===== shared mainloop fragment math: warp tile 64x32, 16 warps (2m x 8n) =====
#define GX_MMA(s)                                                                     \
    {                                                                                 \
        const float* As = sm + (s) * 6144;                                            \
        const float* Bs = As + 2048;                                                  \
        const int kl = lane & 3, dn = lane >> 2;                                      \
        _Pragma("unroll")                                                             \
        for (int ks = 0; ks < 2; ++ks) {                                              \
            int lsw = aswz(lane, ks);                                                 \
            uint4 af[4];                                                              \
            _Pragma("unroll")                                                         \
            for (int mt = 0; mt < 4; ++mt)                                            \
                af[mt] = *reinterpret_cast<const uint4*>(                             \
                    As + ((ks * 8 + wm * 4 + mt) * 32 + lsw) * 4);                    \
            uint2 bf[4];                                                              \
            _Pragma("unroll")                                                         \
            for (int nt = 0; nt < 4; ++nt) {                                          \
                int pn = (wn * 32 + nt * 8 + dn) ^ (kl << 3);                         \
                bf[nt].x = __float_as_uint(Bs[(ks * 8 + kl) * 256 + pn]);             \
                bf[nt].y = __float_as_uint(Bs[(ks * 8 + kl + 4) * 256 + pn]);         \
            }                                                                         \
            _Pragma("unroll")                                                         \
            for (int mt = 0; mt < 4; ++mt)                                            \
                _Pragma("unroll")                                                     \
                for (int nt = 0; nt < 4; ++nt)                                        \
                    mma_tf32(acc[mt][nt], (const uint32_t*)&af[mt], (const uint32_t*)&bf[nt]); \
        }                                                                             \
    }

// ============================================================================
// GEMM1: act = tf32( gelu(X@wg) * (X@wu) )
// CTA: M=128 x Nphys=256 (128 logical I cols; phys 8-col block b: even=wg, odd=wu)
// 512 threads, warp 64x32 (2m x 8n). K=1024, kb=16, 3-stage, 1 sync/chunk.
// ============================================================================
__global__ __launch_bounds__(512, 1)
void gemm1_kernel(const float* __restrict__ hs,
                  const float* __restrict__ wg,
                  const float* __restrict__ wu) {
    const int e = blockIdx.y;
    const int count = g_count[e];
    const int m0 = blockIdx.z * 128;
    if (m0 >= count) return;
    const int n0 = blockIdx.x * 128;          // logical I-column base

    extern __shared__ float sm[];
    __shared__ int rowtok[128];

    const int tid = threadIdx.x, wid = tid >> 5, lane = tid & 31;
    const int wm = wid & 1, wn = wid >> 1;    // 2 x 8 warps of 64x32

    if (tid < 128) {
        int gp = m0 + tid;
        rowtok[tid] = (gp < count) ? g_tok[e][gp] : -1;
    }
    __syncthreads();

    const float* wgp = wg + (size_t)e * H_DIM * I_DIM + n0;
    const float* wup = wu + (size_t)e * H_DIM * I_DIM + n0;

    float acc[4][4][4];
#pragma unroll
    for (int i = 0; i < 4; i++)
#pragma unroll
        for (int j = 0; j < 4; j++)
#pragma unroll
            for (int q = 0; q < 4; q++) acc[i][j][q] = 0.f;

    float4 rA, rB4[2];

#define G1_LOAD(k0)                                                                   \
    {                                                                                 \
        {                                                                             \
            int m = tid >> 2, kq = (tid & 3) << 2;                                    \
            int tok = rowtok[m];                                                      \
            rA = (tok >= 0)                                                           \
                ? *reinterpret_cast<const float4*>(hs + (size_t)tok * H_DIM + (k0) + kq) \
                : make_float4(0.f, 0.f, 0.f, 0.f);                                    \
        }                                                                             \
        _Pragma("unroll")                                                             \
        for (int it = 0; it < 2; ++it) {                                              \
            int f = tid + it * 512;                                                   \
            int n4 = f & 63, k = f >> 6;                                              \
            int blk = n4 >> 1;                                                        \
            const float* bsrc = (blk & 1) ? wup : wgp;                                \
            int srcoff = (blk >> 1) * 8 + (n4 & 1) * 4;                               \
            rB4[it] = *reinterpret_cast<const float4*>(                               \
                bsrc + (size_t)((k0) + k) * I_DIM + srcoff);                          \
        }                                                                             \
    }

#define G1_STORE(s)                                                                   \
    {                                                                                 \
        float* As = sm + (s) * 6144;                                                  \
        float* Bs = As + 2048;                                                        \
        {                                                                             \
            int m = tid >> 2, kq = (tid & 3) << 2;                                    \
            int ks = kq >> 3, chalf = (kq >> 2) & 1;                                  \
            int reg = ((m >> 3) & 1) + 2 * chalf;                                     \
            int mt = m >> 4, lane0 = (m & 7) << 2;                                    \
            int slotb = (ks * 8 + mt) * 32;                                           \
            float v[4] = {rA.x, rA.y, rA.z, rA.w};                                    \
            _Pragma("unroll")                                                         \
            for (int j = 0; j < 4; ++j)                                               \
                As[(slotb + aswz(lane0 + j, ks)) * 4 + reg] = to_tf32f(v[j]);         \
        }                                                                             \
        _Pragma("unroll")                                                             \
        for (int it = 0; it < 2; ++it) {                                              \
            int f = tid + it * 512;                                                   \
            int n4 = f & 63, k = f >> 6;                                              \
            int pn4 = n4 ^ ((k & 3) << 1);                                            \
            float4 o = make_float4(to_tf32f(rB4[it].x), to_tf32f(rB4[it].y),          \
                                   to_tf32f(rB4[it].z), to_tf32f(rB4[it].w));         \
            *reinterpret_cast<float4*>(Bs + k * 256 + pn4 * 4) = o;                   \
        }                                                                             \
    }

    const int NC = H_DIM / 16;   // 64
    G1_LOAD(0);
    G1_STORE(0);
    G1_LOAD(16);
    __syncthreads();
    {
        int cs = 0;
        for (int c = 0; c < NC; ++c) {
            int st = (cs == 2) ? 0 : cs + 1;
            if (c + 1 < NC) G1_STORE(st);
            if (c + 2 < NC) G1_LOAD((c + 2) * 16);
            GX_MMA(cs);
            __syncthreads();
            cs = st;
        }
    }

    // ---- epilogue: pairs (acc[mt][2j], acc[mt][2j+1]) = (g,u), logical block 2wn+j ----
#pragma unroll
    for (int mt = 0; mt < 4; ++mt) {
        int row_base = wm * 64 + mt * 16 + (lane >> 2);
#pragma unroll
        for (int h = 0; h < 2; ++h) {
            int gpos = m0 + row_base + h * 8;
            if (gpos >= count) continue;
            float* dst = g_act + ((size_t)e * T_TOK + gpos) * I_DIM + n0;
#pragma unroll
            for (int j = 0; j < 2; ++j) {
                int col = (2 * wn + j) * 8 + (lane & 3) * 2;
                float2 o;
                o.x = to_tf32f(gelu_tanh(acc[mt][2 * j][2 * h])     * acc[mt][2 * j + 1][2 * h]);
                o.y = to_tf32f(gelu_tanh(acc[mt][2 * j][2 * h + 1]) * acc[mt][2 * j + 1][2 * h + 1]);
                *reinterpret_cast<float2*>(dst + col) = o;
            }
        }
    }
#undef G1_LOAD
#undef G1_STORE
}

// ============================================================================
// GEMM2: y = weight * (act @ wd). CTA 128x256, 512 threads, warp 64x32,
// K=2048, kb=16, 3-stage, 1 sync/chunk.
// ============================================================================
__global__ __launch_bounds__(512, 1)
void gemm2_kernel(const float* __restrict__ wd) {
    const int e = blockIdx.y;
    const int count = g_count[e];
    const int m0 = blockIdx.z * 128;
    if (m0 >= count) return;
    const int n0 = blockIdx.x * 256;

    extern __shared__ float sm[];

    const int tid = threadIdx.x, wid = tid >> 5, lane = tid & 31;
    const int wm = wid & 1, wn = wid >> 1;

    const float* actp = g_act + (size_t)e * T_TOK * I_DIM;
    const float* wdp  = wd + (size_t)e * I_DIM * H_DIM + n0;

    float acc[4][4][4];
#pragma unroll
    for (int i = 0; i < 4; i++)
#pragma unroll
        for (int j = 0; j < 4; j++)
#pragma unroll
            for (int q = 0; q < 4; q++) acc[i][j][q] = 0.f;

    float4 rA, rB4[2];

#define G2_LOAD(k0)                                                                   \
    {                                                                                 \
        {                                                                             \
            int m = tid >> 2, kq = (tid & 3) << 2;                                    \
            int gp = m0 + m;                                                          \
            rA = (gp < count)                                                         \
                ? *reinterpret_cast<const float4*>(actp + (size_t)gp * I_DIM + (k0) + kq) \
                : make_float4(0.f, 0.f, 0.f, 0.f);                                    \
        }                                                                             \
        _Pragma("unroll")                                                             \
        for (int it = 0; it < 2; ++it) {                                              \
            int f = tid + it * 512;                                                   \
            int n4 = f & 63, k = f >> 6;                                              \
            rB4[it] = *reinterpret_cast<const float4*>(                               \
                wdp + (size_t)((k0) + k) * H_DIM + n4 * 4);                           \
        }                                                                             \
    }

#define G2_STORE(s)                                                                   \
    {                                                                                 \
        float* As = sm + (s) * 6144;                                                  \
        float* Bs = As + 2048;                                                        \
        {                                                                             \
            int m = tid >> 2, kq = (tid & 3) << 2;                                    \
            int ks = kq >> 3, chalf = (kq >> 2) & 1;                                  \
            int reg = ((m >> 3) & 1) + 2 * chalf;                                     \
            int mt = m >> 4, lane0 = (m & 7) << 2;                                    \
            int slotb = (ks * 8 + mt) * 32;                                           \
            float v[4] = {rA.x, rA.y, rA.z, rA.w};                                    \
            _Pragma("unroll")                                                         \
            for (int j = 0; j < 4; ++j)                                               \
                As[(slotb + aswz(lane0 + j, ks)) * 4 + reg] = v[j];                   \
        }                                                                             \
        _Pragma("unroll")                                                             \
        for (int it = 0; it < 2; ++it) {                                              \
            int f = tid + it * 512;                                                   \
            int n4 = f & 63, k = f >> 6;                                              \
            int pn4 = n4 ^ ((k & 3) << 1);                                            \
            float4 o = make_float4(to_tf32f(rB4[it].x), to_tf32f(rB4[it].y),          \
                                   to_tf32f(rB4[it].z), to_tf32f(rB4[it].w));         \
            *reinterpret_cast<float4*>(Bs + k * 256 + pn4 * 4) = o;                   \
        }                                                                             \
    }

    const int NC = I_DIM / 16;   // 128
    G2_LOAD(0);
    G2_STORE(0);
    G2_LOAD(16);
    __syncthreads();
    {
        int cs = 0;
        for (int c = 0; c < NC; ++c) {
            int st = (cs == 2) ? 0 : cs + 1;
            if (c + 1 < NC) G2_STORE(st);
            if (c + 2 < NC) G2_LOAD((c + 2) * 16);
            GX_MMA(cs);
            __syncthreads();
            cs = st;
        }
    }

    // ---- epilogue: scale by combine weight, write slot buffer ----
#pragma unroll
    for (int mt = 0; mt < 4; ++mt) {
        int row_base = wm * 64 + mt * 16 + (lane >> 2);
#pragma unroll
        for (int h = 0; h < 2; ++h) {
            int gpos = m0 + row_base + h * 8;
            if (gpos >= count) continue;
            float w = g_wt[e][gpos];
            float* dst = g_y + ((size_t)e * T_TOK + gpos) * H_DIM + n0;
#pragma unroll
            for (int nt = 0; nt < 4; ++nt) {
                int col = wn * 32 + nt * 8 + (lane & 3) * 2;
                float2 o;
                o.x = w * acc[mt][nt][2 * h];
                o.y = w * acc[mt][nt][2 * h + 1];
                *reinterpret_cast<float2*>(dst + col) = o;
            }
        }
    }
#undef G2_LOAD
#undef G2_STORE
#undef GX_MMA
}

// ---------------- combine: out[t] = y[slot0] + y[slot1] ----------------
__global__ __launch_bounds__(256) void combine_kernel(float* __restrict__ out) {
    int t = blockIdx.x;
    int s0 = g_slot[t][0], s1 = g_slot[t][1];
    const float4* y0 = reinterpret_cast<const float4*>(g_y + (size_t)s0 * H_DIM);
    const float4* y1 = reinterpret_cast<const float4*>(g_y + (size_t)s1 * H_DIM);
    float4* o = reinterpret_cast<float4*>(out + (size_t)t * H_DIM);
    int c = threadIdx.x;
    float4 a = y0[c], b = y1[c];
    o[c] = make_float4(a.x + b.x, a.y + b.y, a.z + b.z, a.w + b.w);
}

// ---------------- launch ----------------
extern "C" void kernel_launch(void* const* d_in, const int* in_sizes, int n_in,
                              void* d_out, int out_size) {
    const float* hs = (const float*)d_in[0];   // [T, H]
    const float* gw = (const float*)d_in[1];   // [H, E]
    const float* wg = (const float*)d_in[2];   // [E, H, I]
    const float* wu = (const float*)d_in[3];   // [E, H, I]
    const float* wd = (const float*)d_in[4];   // [E, I, H]
    float* out = (float*)d_out;                // [T, H]

    static bool attr_done = false;
    if (!attr_done) {
        cudaFuncSetAttribute(gemm1_kernel, cudaFuncAttributeMaxDynamicSharedMemorySize, 73728);
        cudaFuncSetAttribute(gemm2_kernel, cudaFuncAttributeMaxDynamicSharedMemorySize, 73728);
        attr_done = true;
    }

    zero_counts_kernel<<<1, 32>>>();
    router_kernel<<<T_TOK, 128>>>(hs, gw);

    dim3 g1(I_DIM / 128, E_NUM, T_TOK / 128);   // (16, 8, 16)
    gemm1_kernel<<<g1, 512, 73728>>>(hs, wg, wu);

    dim3 g2(H_DIM / 256, E_NUM, T_TOK / 128);   // (4, 8, 16)
    gemm2_kernel<<<g2, 512, 73728>>>(wd);

    combine_kernel<<<T_TOK, 256>>>(out);
}

// round 11
// speedup vs baseline: 1.1928x; 1.1928x over previous
#include <cuda_runtime.h>
#include <cuda_fp16.h>
#include <math.h>
#include <stdint.h>

#define T_TOK 2048
#define H_DIM 1024
#define E_NUM 8
#define I_DIM 2048

// ---------------- device scratch ----------------
__device__ int    g_count[E_NUM];
__device__ int    g_tok[E_NUM][T_TOK];
__device__ float  g_wt[E_NUM][T_TOK];
__device__ int    g_slot[T_TOK][2];
__device__ __half g_act[(size_t)E_NUM * T_TOK * I_DIM];  // 64 MB fp16
__device__ float  g_y[(size_t)E_NUM * T_TOK * H_DIM];    // 64 MB

// ---------------- helpers ----------------
__device__ __forceinline__ uint32_t f2h2(float lo, float hi) {
    __half2 h;
    h.x = __float2half_rn(lo);
    h.y = __float2half_rn(hi);
    return *reinterpret_cast<uint32_t*>(&h);
}
__device__ __forceinline__ void mma_f16(float* c, const uint32_t* a, const uint32_t* b) {
    asm volatile(
        "mma.sync.aligned.m16n8k16.row.col.f32.f16.f16.f32 "
        "{%0,%1,%2,%3}, {%4,%5,%6,%7}, {%8,%9}, {%0,%1,%2,%3};"
        : "+f"(c[0]), "+f"(c[1]), "+f"(c[2]), "+f"(c[3])
        : "r"(a[0]), "r"(a[1]), "r"(a[2]), "r"(a[3]), "r"(b[0]), "r"(b[1]));
}

// ---------------- small kernels ----------------
__global__ void zero_counts_kernel() {
    if (threadIdx.x < E_NUM) g_count[threadIdx.x] = 0;
}

__global__ void router_kernel(const float* __restrict__ hs, const float* __restrict__ gw) {
    int t = blockIdx.x;
    const float* x = hs + (size_t)t * H_DIM;
    float acc[E_NUM];
#pragma unroll
    for (int e = 0; e < E_NUM; e++) acc[e] = 0.f;
    for (int j = threadIdx.x; j < H_DIM; j += blockDim.x) {
        float xv = x[j];
        const float4* grow = reinterpret_cast<const float4*>(gw + (size_t)j * E_NUM);
        float4 g0 = grow[0], g1 = grow[1];
        acc[0] += xv * g0.x; acc[1] += xv * g0.y; acc[2] += xv * g0.z; acc[3] += xv * g0.w;
        acc[4] += xv * g1.x; acc[5] += xv * g1.y; acc[6] += xv * g1.z; acc[7] += xv * g1.w;
    }
#pragma unroll
    for (int off = 16; off > 0; off >>= 1)
#pragma unroll
        for (int e = 0; e < E_NUM; e++)
            acc[e] += __shfl_xor_sync(0xffffffffu, acc[e], off);
    __shared__ float s[4][E_NUM];
    int warp = threadIdx.x >> 5, lane = threadIdx.x & 31;
    if (lane == 0)
#pragma unroll
        for (int e = 0; e < E_NUM; e++) s[warp][e] = acc[e];
    __syncthreads();
    if (threadIdx.x == 0) {
        float l[E_NUM];
#pragma unroll
        for (int e = 0; e < E_NUM; e++)
            l[e] = tanhf((s[0][e] + s[1][e] + s[2][e] + s[3][e]) * (1.0f / 30.0f));
        int i0 = 0;
#pragma unroll
        for (int e = 1; e < E_NUM; e++) if (l[e] > l[i0]) i0 = e;
        int i1 = (i0 == 0) ? 1 : 0;
#pragma unroll
        for (int e = 0; e < E_NUM; e++) if (e != i0 && l[e] > l[i1]) i1 = e;
        float d  = l[i1] - l[i0];
        float ed = expf(d);
        float inv = 1.0f / (1.0f + ed);
        float p0 = inv, p1 = ed * inv;
        int p = atomicAdd(&g_count[i0], 1);
        g_tok[i0][p] = t; g_wt[i0][p] = p0; g_slot[t][0] = i0 * T_TOK + p;
        p = atomicAdd(&g_count[i1], 1);
        g_tok[i1][p] = t; g_wt[i1][p] = p1; g_slot[t][1] = i1 * T_TOK + p;
    }
}

__device__ __forceinline__ float gelu_tanh(float g) {
    float c = 0.7978845608028654f * (g + 0.044715f * g * g * g);
    return 0.5f * g * (1.0f + tanhf(c));
}

// ===== shared mainloop: fp16 m16n8k16, warp tile 64x32, 16 warps (2m x 8n) ====
// A stage: 2048 words, frag-order ((ks*8+mt)*32+lane)*4+reg
// B stage: 4096 words, [k2 16][256 cols] half2 words, col XOR (kl<<3) swizzle
#define GX_MMA(s)                                                                     \
    {                                                                                 \
        const uint32_t* As = sm32 + (s) * 6144;                                       \
        const uint32_t* Bs = As + 2048;                                               \
        const int kl = lane & 3, dn = lane >> 2;                                      \
        _Pragma("unroll")                                                             \
        for (int ks = 0; ks < 2; ++ks) {                                              \
            uint4 af[4];                                                              \
            _Pragma("unroll")                                                         \
            for (int mt = 0; mt < 4; ++mt)                                            \
                af[mt] = *reinterpret_cast<const uint4*>(                             \
                    As + ((ks * 8 + wm * 4 + mt) * 32 + lane) * 4);                   \
            uint2 bf[4];                                                              \
            _Pragma("unroll")                                                         \
            for (int nt = 0; nt < 4; ++nt) {                                          \
                int pn = (wn * 32 + nt * 8 + dn) ^ (kl << 3);                         \
                bf[nt].x = Bs[(ks * 8 + kl) * 256 + pn];                              \
                bf[nt].y = Bs[(ks * 8 + kl + 4) * 256 + pn];                          \
            }                                                                         \
            _Pragma("unroll")                                                         \
            for (int mt = 0; mt < 4; ++mt)                                            \
                _Pragma("unroll")                                                     \
                for (int nt = 0; nt < 4; ++nt)                                        \
                    mma_f16(acc[mt][nt], (const uint32_t*)&af[mt], (const uint32_t*)&bf[nt]); \
        }                                                                             \
    }

// A store mapping for a 4-float (4-k) group at (m, kq):
//   words (kq,kq+1)->c, (kq+2,kq+3)->c+1; reg = ((kin&8)>>2)+((m&8)>>3)
#define A_STORE_WORDS(As, m, kq, w0, w1)                                              \
    {                                                                                 \
        int kin = (kq) & 15, ks = (kq) >> 4;                                          \
        int c = (kin >> 1) & 3;                                                       \
        int reg = ((kin & 8) >> 2) + (((m) & 8) >> 3);                                \
        int lane0 = (((m) & 7) << 2) + c;                                             \
        int base = ((ks * 8 + ((m) >> 4)) * 32);                                      \
        (As)[(base + lane0) * 4 + reg] = (w0);                                        \
        (As)[(base + lane0 + 1) * 4 + reg] = (w1);                                    \
    }

// ============================================================================
// GEMM1: act_fp16 = gelu(X@wg) * (X@wu)
// CTA: M=128 x Nphys=256 (phys 8-col block b: even=wg blk b/2, odd=wu).
// 512 threads, kb=32, 3-stage, 1 sync/chunk.
// ============================================================================
__global__ __launch_bounds__(512, 1)
void gemm1_kernel(const float* __restrict__ hs,
                  const float* __restrict__ wg,
                  const float* __restrict__ wu) {
    const int e = blockIdx.y;
    const int count = g_count[e];
    const int m0 = blockIdx.z * 128;
    if (m0 >= count) return;
    const int n0 = blockIdx.x * 128;          // logical I-column base

    extern __shared__ uint32_t sm32[];
    __shared__ int rowtok[128];

    const int tid = threadIdx.x, wid = tid >> 5, lane = tid & 31;
    const int wm = wid & 1, wn = wid >> 1;

    if (tid < 128) {
        int gp = m0 + tid;
        rowtok[tid] = (gp < count) ? g_tok[e][gp] : -1;
    }
    __syncthreads();

    const float* wgp = wg + (size_t)e * H_DIM * I_DIM + n0;
    const float* wup = wu + (size_t)e * H_DIM * I_DIM + n0;

    float acc[4][4][4];
#pragma unroll
    for (int i = 0; i < 4; i++)
#pragma unroll
        for (int j = 0; j < 4; j++)
#pragma unroll
            for (int q = 0; q < 4; q++) acc[i][j][q] = 0.f;

    uint2 rAw[2];      // A: 2 packed word-pairs
    uint4 rBw[2];      // B: 2 packed 4-word groups

#define G1_LOAD(k0)                                                                   \
    {                                                                                 \
        _Pragma("unroll")                                                             \
        for (int it = 0; it < 2; ++it) {                                              \
            int f = tid + it * 512;                                                   \
            int m = f >> 3, kq = (f & 7) << 2;                                        \
            int tok = rowtok[m];                                                      \
            float4 v = (tok >= 0)                                                     \
                ? *reinterpret_cast<const float4*>(hs + (size_t)tok * H_DIM + (k0) + kq) \
                : make_float4(0.f, 0.f, 0.f, 0.f);                                    \
            rAw[it].x = f2h2(v.x, v.y);                                               \
            rAw[it].y = f2h2(v.z, v.w);                                               \
        }                                                                             \
        _Pragma("unroll")                                                             \
        for (int it = 0; it < 2; ++it) {                                              \
            int f = tid + it * 512;                                                   \
            int n4 = f & 63, k2 = f >> 6;                                             \
            int blk = n4 >> 1;                                                        \
            const float* bsrc = (blk & 1) ? wup : wgp;                                \
            int srcoff = (blk >> 1) * 8 + (n4 & 1) * 4;                               \
            float4 r0 = *reinterpret_cast<const float4*>(                             \
                bsrc + (size_t)((k0) + 2 * k2) * I_DIM + srcoff);                     \
            float4 r1 = *reinterpret_cast<const float4*>(                             \
                bsrc + (size_t)((k0) + 2 * k2 + 1) * I_DIM + srcoff);                 \
            rBw[it].x = f2h2(r0.x, r1.x);                                             \
            rBw[it].y = f2h2(r0.y, r1.y);                                             \
            rBw[it].z = f2h2(r0.z, r1.z);                                             \
            rBw[it].w = f2h2(r0.w, r1.w);                                             \
        }                                                                             \
    }

#define G1_STORE(s)                                                                   \
    {                                                                                 \
        uint32_t* As = sm32 + (s) * 6144;                                             \
        uint32_t* Bs = As + 2048;                                                     \
        _Pragma("unroll")                                                             \
        for (int it = 0; it < 2; ++it) {                                              \
            int f = tid + it * 512;                                                   \
            int m = f >> 3, kq = (f & 7) << 2;                                        \
            A_STORE_WORDS(As, m, kq, rAw[it].x, rAw[it].y);                           \
        }                                                                             \
        _Pragma("unroll")                                                             \
        for (int it = 0; it < 2; ++it) {                                              \
            int f = tid + it * 512;                                                   \
            int n4 = f & 63, k2 = f >> 6;                                             \
            int pn4 = n4 ^ ((k2 & 3) << 1);                                           \
            *reinterpret_cast<uint4*>(Bs + k2 * 256 + pn4 * 4) = rBw[it];             \
        }                                                                             \
    }

    const int NC = H_DIM / 32;   // 32
    G1_LOAD(0);
    G1_STORE(0);
    G1_LOAD(32);
    __syncthreads();
    {
        int cs = 0;
        for (int c = 0; c < NC; ++c) {
            int st = (cs == 2) ? 0 : cs + 1;
            if (c + 1 < NC) G1_STORE(st);
            if (c + 2 < NC) G1_LOAD((c + 2) * 32);
            GX_MMA(cs);
            __syncthreads();
            cs = st;
        }
    }

    // ---- epilogue: pairs (acc[mt][2j], acc[mt][2j+1]) = (g,u); write fp16 ----
#pragma unroll
    for (int mt = 0; mt < 4; ++mt) {
        int row_base = wm * 64 + mt * 16 + (lane >> 2);
#pragma unroll
        for (int h = 0; h < 2; ++h) {
            int gpos = m0 + row_base + h * 8;
            if (gpos >= count) continue;
            __half* dst = g_act + ((size_t)e * T_TOK + gpos) * I_DIM + n0;
#pragma unroll
            for (int j = 0; j < 2; ++j) {
                int col = (2 * wn + j) * 8 + (lane & 3) * 2;
                uint32_t w = f2h2(
                    gelu_tanh(acc[mt][2 * j][2 * h])     * acc[mt][2 * j + 1][2 * h],
                    gelu_tanh(acc[mt][2 * j][2 * h + 1]) * acc[mt][2 * j + 1][2 * h + 1]);
                *reinterpret_cast<uint32_t*>(dst + col) = w;
            }
        }
    }
#undef G1_LOAD
#undef G1_STORE
}

// ============================================================================
// GEMM2: y = weight * (act_fp16 @ wd). CTA 128x256, 512 thr, kb=32, 3-stage.
// ============================================================================
__global__ __launch_bounds__(512, 1)
void gemm2_kernel(const float* __restrict__ wd) {
    const int e = blockIdx.y;
    const int count = g_count[e];
    const int m0 = blockIdx.z * 128;
    if (m0 >= count) return;
    const int n0 = blockIdx.x * 256;

    extern __shared__ uint32_t sm32[];

    const int tid = threadIdx.x, wid = tid >> 5, lane = tid & 31;
    const int wm = wid & 1, wn = wid >> 1;

    const __half* actp = g_act + (size_t)e * T_TOK * I_DIM;
    const float*  wdp  = wd + (size_t)e * I_DIM * H_DIM + n0;

    float acc[4][4][4];
#pragma unroll
    for (int i = 0; i < 4; i++)
#pragma unroll
        for (int j = 0; j < 4; j++)
#pragma unroll
            for (int q = 0; q < 4; q++) acc[i][j][q] = 0.f;

    uint2 rAw[2];
    uint4 rBw[2];

#define G2_LOAD(k0)                                                                   \
    {                                                                                 \
        _Pragma("unroll")                                                             \
        for (int it = 0; it < 2; ++it) {                                              \
            int f = tid + it * 512;                                                   \
            int m = f >> 3, kq = (f & 7) << 2;                                        \
            int gp = m0 + m;                                                          \
            rAw[it] = (gp < count)                                                    \
                ? *reinterpret_cast<const uint2*>(actp + (size_t)gp * I_DIM + (k0) + kq) \
                : make_uint2(0u, 0u);                                                 \
        }                                                                             \
        _Pragma("unroll")                                                             \
        for (int it = 0; it < 2; ++it) {                                              \
            int f = tid + it * 512;                                                   \
            int n4 = f & 63, k2 = f >> 6;                                             \
            float4 r0 = *reinterpret_cast<const float4*>(                             \
                wdp + (size_t)((k0) + 2 * k2) * H_DIM + n4 * 4);                      \
            float4 r1 = *reinterpret_cast<const float4*>(                             \
                wdp + (size_t)((k0) + 2 * k2 + 1) * H_DIM + n4 * 4);                  \
            rBw[it].x = f2h2(r0.x, r1.x);                                             \
            rBw[it].y = f2h2(r0.y, r1.y);                                             \
            rBw[it].z = f2h2(r0.z, r1.z);                                             \
            rBw[it].w = f2h2(r0.w, r1.w);                                             \
        }                                                                             \
    }

#define G2_STORE(s)                                                                   \
    {                                                                                 \
        uint32_t* As = sm32 + (s) * 6144;                                             \
        uint32_t* Bs = As + 2048;                                                     \
        _Pragma("unroll")                                                             \
        for (int it = 0; it < 2; ++it) {                                              \
            int f = tid + it * 512;                                                   \
            int m = f >> 3, kq = (f & 7) << 2;                                        \
            A_STORE_WORDS(As, m, kq, rAw[it].x, rAw[it].y);                           \
        }                                                                             \
        _Pragma("unroll")                                                             \
        for (int it = 0; it < 2; ++it) {                                              \
            int f = tid + it * 512;                                                   \
            int n4 = f & 63, k2 = f >> 6;                                             \
            int pn4 = n4 ^ ((k2 & 3) << 1);                                           \
            *reinterpret_cast<uint4*>(Bs + k2 * 256 + pn4 * 4) = rBw[it];             \
        }                                                                             \
    }

    const int NC = I_DIM / 32;   // 64
    G2_LOAD(0);
    G2_STORE(0);
    G2_LOAD(32);
    __syncthreads();
    {
        int cs = 0;
        for (int c = 0; c < NC; ++c) {
            int st = (cs == 2) ? 0 : cs + 1;
            if (c + 1 < NC) G2_STORE(st);
            if (c + 2 < NC) G2_LOAD((c + 2) * 32);
            GX_MMA(cs);
            __syncthreads();
            cs = st;
        }
    }

    // ---- epilogue: scale by combine weight, write slot buffer ----
#pragma unroll
    for (int mt = 0; mt < 4; ++mt) {
        int row_base = wm * 64 + mt * 16 + (lane >> 2);
#pragma unroll
        for (int h = 0; h < 2; ++h) {
            int gpos = m0 + row_base + h * 8;
            if (gpos >= count) continue;
            float w = g_wt[e][gpos];
            float* dst = g_y + ((size_t)e * T_TOK + gpos) * H_DIM + n0;
#pragma unroll
            for (int nt = 0; nt < 4; ++nt) {
                int col = wn * 32 + nt * 8 + (lane & 3) * 2;
                float2 o;
                o.x = w * acc[mt][nt][2 * h];
                o.y = w * acc[mt][nt][2 * h + 1];
                *reinterpret_cast<float2*>(dst + col) = o;
            }
        }
    }
#undef G2_LOAD
#undef G2_STORE
#undef GX_MMA
}

// ---------------- combine: out[t] = y[slot0] + y[slot1] ----------------
__global__ __launch_bounds__(256) void combine_kernel(float* __restrict__ out) {
    int t = blockIdx.x;
    int s0 = g_slot[t][0], s1 = g_slot[t][1];
    const float4* y0 = reinterpret_cast<const float4*>(g_y + (size_t)s0 * H_DIM);
    const float4* y1 = reinterpret_cast<const float4*>(g_y + (size_t)s1 * H_DIM);
    float4* o = reinterpret_cast<float4*>(out + (size_t)t * H_DIM);
    int c = threadIdx.x;
    float4 a = y0[c], b = y1[c];
    o[c] = make_float4(a.x + b.x, a.y + b.y, a.z + b.z, a.w + b.w);
}

// ---------------- launch ----------------
extern "C" void kernel_launch(void* const* d_in, const int* in_sizes, int n_in,
                              void* d_out, int out_size) {
    const float* hs = (const float*)d_in[0];   // [T, H]
    const float* gw = (const float*)d_in[1];   // [H, E]
    const float* wg = (const float*)d_in[2];   // [E, H, I]
    const float* wu = (const float*)d_in[3];   // [E, H, I]
    const float* wd = (const float*)d_in[4];   // [E, I, H]
    float* out = (float*)d_out;                // [T, H]

    static bool attr_done = false;
    if (!attr_done) {
        cudaFuncSetAttribute(gemm1_kernel, cudaFuncAttributeMaxDynamicSharedMemorySize, 73728);
        cudaFuncSetAttribute(gemm2_kernel, cudaFuncAttributeMaxDynamicSharedMemorySize, 73728);
        attr_done = true;
    }

    zero_counts_kernel<<<1, 32>>>();
    router_kernel<<<T_TOK, 128>>>(hs, gw);

    dim3 g1(I_DIM / 128, E_NUM, T_TOK / 128);   // (16, 8, 16)
    gemm1_kernel<<<g1, 512, 73728>>>(hs, wg, wu);

    dim3 g2(H_DIM / 256, E_NUM, T_TOK / 128);   // (4, 8, 16)
    gemm2_kernel<<<g2, 512, 73728>>>(wd);

    combine_kernel<<<T_TOK, 256>>>(out);
}